// round 7
// baseline (speedup 1.0000x reference)
#include <cuda_runtime.h>

// ---------------- problem constants ----------------
#define BATCH   256
#define NSAMP   16000
#define CCH     32
#define KTAP    64
#define NCHUNK  125          // 128-sample chunks covering 16000 samples
#define TSTEPS  124
#define HID     50
#define HIDP    52           // padded row stride for SufW / curB
#define OUT     10
#define ANS     10

#define GROUP   8            // chunks per conv tile (one per warp)
#define SEG     (GROUP*128)  // 1024 positions per tile
#define SWIN    1088         // staged window length per shifted copy
#define SPITCH  1104         // padded copy pitch (floats); *4 bytes is 16B multiple
#define NGRP    16           // tiles per batch row
#define CONV_CTAS 304        // 2 per SM on 152-SM GB300

// ---------------- device scratch (no allocs allowed) ----------------
__device__ float  S_buf[BATCH * NCHUNK * CCH];                  // per-chunk relu sums
__device__ __align__(16) float SufW_g[CCH * (ANS + 1) * HIDP];  // padded suffix sums

// ---------------- helpers ----------------
__device__ __forceinline__ unsigned s2u(const void* p) {
    return (unsigned)__cvta_generic_to_shared(p);
}
#define FFMA2(acc, a, b) \
    asm("fma.rn.f32x2 %0, %1, %2, %0;" : "+l"(acc) : "l"(a), "l"(b))
#define LDSV2(lo, hi, addr) \
    asm("ld.shared.v2.b64 {%0, %1}, [%2];" : "=l"(lo), "=l"(hi) : "r"(addr))

// ---------------- kernel A: suffix sums of W_bushy (padded layout) ----------------
__global__ void prep_kernel(const float* __restrict__ Wb) {
    int id = blockIdx.x * 256 + threadIdx.x;
    if (id < CCH * (ANS + 1)) {               // zero pad columns
        SufW_g[id * HIDP + 50] = 0.0f;
        SufW_g[id * HIDP + 51] = 0.0f;
    }
    if (id >= HID * CCH) return;
    int h = id / CCH;
    int c = id % CCH;
    SufW_g[(c * 11 + 10) * HIDP + h] = 0.0f;
    float v[ANS];
    #pragma unroll
    for (int a = 0; a < ANS; a++)             // independent loads (ILP)
        v[a] = Wb[h * (CCH * ANS) + c * ANS + a];
    float s = 0.0f;
    #pragma unroll
    for (int a = ANS - 1; a >= 0; a--) {
        s += v[a];
        SufW_g[(c * 11 + a) * HIDP + h] = s;
    }
}

// ---------------- kernel B: persistent fused conv + relu + chunk-sum ----------------
// 304 persistent CTAs, 256 threads. Tiles T: grp = T>>8 (position group), b = T&255.
// Double-buffered smem; next tile staged via cp.async while computing current.
__device__ __forceinline__ void stage_tile_async(float (*buf)[SPITCH],
                                                 const float* __restrict__ audio,
                                                 int T, int tid) {
    const int grp = T >> 8;
    const int b   = T & (BATCH - 1);
    const int P0  = grp * SEG;
    const float* abase = audio + b * NSAMP;
    if (grp > 0 && grp < NGRP - 1) {
        // interior: unguarded 4B cp.async
        #pragma unroll
        for (int s = 0; s < 4; s++) {
            #pragma unroll 1
            for (int i = tid; i < SWIN; i += 256) {
                const float* src = abase + (P0 - 31 + s + i);
                unsigned dst = s2u(&buf[s][i]);
                asm volatile("cp.async.ca.shared.global [%0], [%1], 4;"
                             :: "r"(dst), "l"(src));
            }
        }
    } else {
        // boundary: guarded synchronous loads (visibility via later __syncthreads)
        #pragma unroll
        for (int s = 0; s < 4; s++) {
            #pragma unroll 1
            for (int i = tid; i < SWIN; i += 256) {
                int n = P0 - 31 + s + i;
                buf[s][i] = (n >= 0 && n < NSAMP) ? abase[n] : 0.0f;
            }
        }
    }
}

__global__ void __launch_bounds__(256, 2) conv_pool_kernel(const float* __restrict__ audio,
                                                           const float* __restrict__ gt,
                                                           int ntiles) {
    __shared__ __align__(16) float s_copy[2][4][SPITCH];
    __shared__ float s_gt[KTAP * 33];                  // swizzled taps [k*33+c]

    const int tid = threadIdx.x;
    const int c   = tid & 31;    // channel = lane
    const int g   = tid >> 5;    // warp id = local chunk

    // stage taps (sync ld/st, covered by the first __syncthreads)
    for (int t = tid; t < CCH * KTAP; t += 256) {
        int cc = t >> 6, k = t & 63;
        s_gt[k * 33 + cc] = gt[t];
    }

    int T = blockIdx.x;
    if (T < ntiles) stage_tile_async(s_copy[0], audio, T, tid);
    asm volatile("cp.async.commit_group;");
    __syncthreads();                           // s_gt ready

    // packed tap pairs: kp[j] = {t[2j], t[2j+1]}
    unsigned long long kp[32];
    #pragma unroll
    for (int j = 0; j < 32; j++) {
        float t0 = s_gt[(2 * j) * 33 + c];
        float t1 = s_gt[(2 * j + 1) * 33 + c];
        asm("mov.b64 %0, {%1, %2};" : "=l"(kp[j]) : "f"(t0), "f"(t1));
    }

    int pb = 0;
    #pragma unroll 1
    for (; T < ntiles; T += CONV_CTAS) {
        // issue next tile into the other buffer, then wait for current
        int Tn = T + CONV_CTAS;
        if (Tn < ntiles) stage_tile_async(s_copy[pb ^ 1], audio, Tn, tid);
        asm volatile("cp.async.commit_group;");
        asm volatile("cp.async.wait_group 1;" ::: "memory");
        __syncthreads();

        const unsigned sbase = s2u(&s_copy[pb][0][0]);
        float chunkacc = 0.0f;

        #pragma unroll 1
        for (int pass = 0; pass < 16; pass++) {
            const int h  = pass >> 2;
            const int c4 = pass & 3;
            const int base = g * 128 + 32 * h;
            const unsigned addr = sbase + (unsigned)((c4 * SPITCH + base) * 4);

            unsigned long long accL[8], accH[8];
            #pragma unroll
            for (int j = 0; j < 8; j++) { accL[j] = 0ull; accH[j] = 0ull; }

            #pragma unroll
            for (int u = 0; u < 23; u++) {
                unsigned long long lo, hi;
                LDSV2(lo, hi, addr + 16u * (unsigned)u);
                #pragma unroll
                for (int j = 0; j < 8; j++) {
                    const int m = u - j;
                    if (m >= 0 && m < 16) {
                        FFMA2(accL[j], lo, kp[2 * m]);
                        FFMA2(accH[j], hi, kp[2 * m + 1]);
                    }
                }
            }

            #pragma unroll
            for (int j = 0; j < 8; j++) {
                float l0, l1, h0, h1;
                asm("mov.b64 {%0, %1}, %2;" : "=f"(l0), "=f"(l1) : "l"(accL[j]));
                asm("mov.b64 {%0, %1}, %2;" : "=f"(h0), "=f"(h1) : "l"(accH[j]));
                float y = (l0 + l1) + (h0 + h1);
                chunkacc += fmaxf(y, 0.0f);
            }
        }

        const int grp = T >> 8;
        const int b   = T & (BATCH - 1);
        const int j   = grp * GROUP + g;
        if (j < NCHUNK)
            S_buf[(b * NCHUNK + j) * CCH + c] = chunkacc;

        __syncthreads();   // all warps done with buf[pb] before it is restaged
        pb ^= 1;
    }
}

// ---------------- kernel C: merged gather + warp scan, one block per batch ----------------
// 256 threads: phase 0 AN offsets, phase 1 SufW gather -> sCurB (smem),
// then warps 1-7 exit and warp 0 runs the 124-step LIF scan with all
// IC/AC weights held in registers.
__global__ void __launch_bounds__(256, 2) scan_kernel(const float* __restrict__ Wic,
                                                      const float* __restrict__ Wac,
                                                      float* __restrict__ out, int half) {
    const int b = blockIdx.x;
    __shared__ __align__(16) float  sCurB[TSTEPS * HIDP];
    __shared__ unsigned short sOff[TSTEPS * CCH];
    __shared__ __align__(8) float sSpkB[52];
    __shared__ __align__(8) float sSpkIC[52];

    const int tid = threadIdx.x;

    // ---- phase 0: per-(t,c) suffix offsets ----
    for (int x = tid; x < TSTEPS * CCH; x += 256) {
        int t = x >> 5, c = x & 31;
        float s0 = S_buf[(b * NCHUNK + t) * CCH + c];
        float s1 = S_buf[(b * NCHUNK + t + 1) * CCH + c];
        float env = (s0 + s1) * (1.0f / 256.0f);
        int cnt = 0;
        #pragma unroll
        for (int a = 0; a < ANS; a++) {
            float sc = 0.5f + (float)a * (1.0f / 9.0f);
            cnt += (env * sc - 0.5f) > 0.0f;
        }
        sOff[x] = (unsigned short)((c * 11 + (ANS - cnt)) * HIDP);
    }
    __syncthreads();

    // ---- phase 1: bushy input currents into smem ----
    for (int x = tid; x < TSTEPS * (HIDP / 4); x += 256) {
        int t = x / (HIDP / 4);
        int q = x - t * (HIDP / 4);
        const unsigned short* off = &sOff[t * CCH];
        float4 acc0 = make_float4(0.f, 0.f, 0.f, 0.f);
        float4 acc1 = make_float4(0.f, 0.f, 0.f, 0.f);
        #pragma unroll 4
        for (int c = 0; c < CCH; c += 2) {
            float4 v0 = __ldg((const float4*)(SufW_g + off[c] + 4 * q));
            float4 v1 = __ldg((const float4*)(SufW_g + off[c + 1] + 4 * q));
            acc0.x += v0.x; acc0.y += v0.y; acc0.z += v0.z; acc0.w += v0.w;
            acc1.x += v1.x; acc1.y += v1.y; acc1.z += v1.z; acc1.w += v1.w;
        }
        float4 r;
        r.x = acc0.x + acc1.x; r.y = acc0.y + acc1.y;
        r.z = acc0.z + acc1.z; r.w = acc0.w + acc1.w;
        *(float4*)&sCurB[t * HIDP + 4 * q] = r;
    }
    __syncthreads();

    if (tid >= 32) return;      // warps 1-7 done
    const int l = tid;

    // ---- load weights into registers (unrolled, compile-time indices) ----
    const bool lane18 = (l < 18);
    const bool lane10 = (l < 10);
    float2 wA[25], wB[25], wC[25];
    {
        const float* rowA = Wic + l * HID;
        const float* rowB = Wic + (lane18 ? (l + 32) : l) * HID;
        const float* rowC = Wac + (lane10 ? l : 0) * HID;
        #pragma unroll
        for (int j = 0; j < 25; j++) {
            wA[j] = make_float2(__ldg(rowA + 2 * j), __ldg(rowA + 2 * j + 1));
            float2 vb = make_float2(__ldg(rowB + 2 * j), __ldg(rowB + 2 * j + 1));
            wB[j] = lane18 ? vb : make_float2(0.f, 0.f);
            wC[j] = make_float2(__ldg(rowC + 2 * j), __ldg(rowC + 2 * j + 1));
        }
    }

    float memB0 = 0.f, memB1 = 0.f, memIC0 = 0.f, memIC1 = 0.f, memAC = 0.f;
    const float beta = 0.95f;

    for (int t = 0; t < TSTEPS; t++) {
        const float* cb = sCurB + t * HIDP;
        // ---- bushy LIF ----
        float cur0 = cb[l];
        float cur1 = cb[32 + l];          // lanes >=18 read pad/junk; never used
        memB0 = fmaf(beta, memB0, cur0);
        memB1 = fmaf(beta, memB1, cur1);
        float s0 = (memB0 > 1.0f) ? 1.0f : 0.0f;
        float s1 = (memB1 > 1.0f) ? 1.0f : 0.0f;
        memB0 -= s0; memB1 -= s1;
        sSpkB[l] = s0;
        if (lane18) sSpkB[32 + l] = s1;
        __syncwarp();

        // ---- inferior colliculus LIF (register weights) ----
        {
            float a0 = 0.f, a1 = 0.f, a2 = 0.f, a3 = 0.f;
            #pragma unroll
            for (int j = 0; j < 25; j++) {
                float2 sp = *(const float2*)&sSpkB[2 * j];
                a0 = fmaf(sp.x, wA[j].x, a0);
                a1 = fmaf(sp.y, wA[j].y, a1);
                a2 = fmaf(sp.x, wB[j].x, a2);
                a3 = fmaf(sp.y, wB[j].y, a3);
            }
            memIC0 = fmaf(beta, memIC0, a0 + a1);
            memIC1 = fmaf(beta, memIC1, a2 + a3);
        }
        float u0 = (memIC0 > 1.0f) ? 1.0f : 0.0f;
        float u1 = (memIC1 > 1.0f) ? 1.0f : 0.0f;
        memIC0 -= u0; memIC1 -= u1;
        sSpkIC[l] = u0;
        if (lane18) sSpkIC[32 + l] = u1;
        __syncwarp();

        // ---- audio cortex LIF + output ----
        {
            float a0 = 0.f, a1 = 0.f;
            #pragma unroll
            for (int j = 0; j < 25; j++) {
                float2 sp = *(const float2*)&sSpkIC[2 * j];
                a0 = fmaf(sp.x, wC[j].x, a0);
                a1 = fmaf(sp.y, wC[j].y, a1);
            }
            memAC = fmaf(beta, memAC, a0 + a1);
            float sa = (memAC > 1.0f) ? 1.0f : 0.0f;
            memAC -= sa;
            if (lane10) {
                int idx = (b * TSTEPS + t) * OUT + l;
                out[idx] = sa;
                out[half + idx] = memAC;
            }
        }
    }
}

// ---------------- launch ----------------
extern "C" void kernel_launch(void* const* d_in, const int* in_sizes, int n_in,
                              void* d_out, int out_size) {
    const float* audio = (const float*)d_in[0];
    const float* gt    = (const float*)d_in[1];
    const float* Wb    = (const float*)d_in[2];
    const float* Wic   = (const float*)d_in[3];
    const float* Wac   = (const float*)d_in[4];
    float* out = (float*)d_out;

    int B = in_sizes[0] / NSAMP;   // 256
    int half = out_size / 2;       // B*T*OUT
    int ntiles = NGRP * B;

    prep_kernel<<<7, 256>>>(Wb);
    conv_pool_kernel<<<CONV_CTAS, 256>>>(audio, gt, ntiles);
    scan_kernel<<<B, 256>>>(Wic, Wac, out, half);
}

// round 8
// speedup vs baseline: 1.0788x; 1.0788x over previous
#include <cuda_runtime.h>

// ---------------- problem constants ----------------
#define BATCH   256
#define NSAMP   16000
#define CCH     32
#define KTAP    64
#define NCHUNK  125          // 128-sample chunks covering 16000 samples
#define TSTEPS  124
#define HID     50
#define HIDP    52           // padded row stride for SufW / curB
#define OUT     10
#define ANS     10

#define GROUP   8            // chunks per conv block (one per warp)
#define SEG     (GROUP*128)  // 1024 positions per block
#define SWIN    1088         // staged window length per shifted copy
#define SPITCH  1104         // padded copy pitch (floats); *4 bytes is 16B multiple

#define SUFW_N  (CCH * (ANS + 1) * HIDP)   // 18304 floats
#define CURB_N  (TSTEPS * HIDP)            // 6448 floats
#define SCAN_DYN_BYTES ((SUFW_N + CURB_N) * 4)

// ---------------- device scratch (no allocs allowed) ----------------
__device__ float  S_buf[BATCH * NCHUNK * CCH];                  // per-chunk relu sums
__device__ __align__(16) float SufW_g[SUFW_N];                  // padded suffix sums

// ---------------- helpers ----------------
__device__ __forceinline__ unsigned s2u(const void* p) {
    return (unsigned)__cvta_generic_to_shared(p);
}
#define FFMA2(acc, a, b) \
    asm("fma.rn.f32x2 %0, %1, %2, %0;" : "+l"(acc) : "l"(a), "l"(b))
#define LDSV2(lo, hi, addr) \
    asm("ld.shared.v2.b64 {%0, %1}, [%2];" : "=l"(lo), "=l"(hi) : "r"(addr))

// ---------------- kernel A: suffix sums of W_bushy (padded layout) ----------------
__global__ void prep_kernel(const float* __restrict__ Wb) {
    int id = blockIdx.x * 256 + threadIdx.x;
    if (id < CCH * (ANS + 1)) {               // zero pad columns
        SufW_g[id * HIDP + 50] = 0.0f;
        SufW_g[id * HIDP + 51] = 0.0f;
    }
    if (id >= HID * CCH) return;
    int h = id / CCH;
    int c = id % CCH;
    SufW_g[(c * 11 + 10) * HIDP + h] = 0.0f;
    float v[ANS];
    #pragma unroll
    for (int a = 0; a < ANS; a++)             // independent loads (ILP)
        v[a] = Wb[h * (CCH * ANS) + c * ANS + a];
    float s = 0.0f;
    #pragma unroll
    for (int a = ANS - 1; a >= 0; a--) {
        s += v[a];
        SufW_g[(c * 11 + a) * HIDP + h] = s;
    }
}

// ---------------- kernel B: fused gammatone conv + relu + chunk-sum ----------------
// (round-6 version: grid (16, BATCH), 256 threads, guarded sync staging)
__global__ void __launch_bounds__(256, 2) conv_pool_kernel(const float* __restrict__ audio,
                                                           const float* __restrict__ gt) {
    const int grp = blockIdx.x;
    const int b   = blockIdx.y;
    __shared__ __align__(16) float s_copy[4][SPITCH];  // 4 shifted copies of audio window
    __shared__ float s_gt[KTAP * 33];                  // swizzled taps [k*33+c]

    const int tid = threadIdx.x;
    const int P0  = grp * SEG;
    const float* abase = audio + b * NSAMP;

    #pragma unroll
    for (int s = 0; s < 4; s++) {
        for (int i = tid; i < SWIN; i += 256) {
            int n = P0 - 31 + i + s;
            s_copy[s][i] = (n >= 0 && n < NSAMP) ? abase[n] : 0.0f;
        }
    }
    for (int t = tid; t < CCH * KTAP; t += 256) {
        int c = t >> 6, k = t & 63;
        s_gt[k * 33 + c] = gt[t];
    }
    __syncthreads();

    const int c = tid & 31;   // channel = lane
    const int g = tid >> 5;   // warp id = local chunk

    unsigned long long kp[32];
    #pragma unroll
    for (int j = 0; j < 32; j++) {
        float t0 = s_gt[(2 * j) * 33 + c];
        float t1 = s_gt[(2 * j + 1) * 33 + c];
        asm("mov.b64 %0, {%1, %2};" : "=l"(kp[j]) : "f"(t0), "f"(t1));
    }

    const unsigned sbase = s2u(&s_copy[0][0]);
    float chunkacc = 0.0f;

    #pragma unroll 1
    for (int pass = 0; pass < 16; pass++) {
        const int h  = pass >> 2;
        const int c4 = pass & 3;
        const int base = g * 128 + 32 * h;
        const unsigned addr = sbase + (unsigned)((c4 * SPITCH + base) * 4);

        unsigned long long accL[8], accH[8];
        #pragma unroll
        for (int j = 0; j < 8; j++) { accL[j] = 0ull; accH[j] = 0ull; }

        #pragma unroll
        for (int u = 0; u < 23; u++) {
            unsigned long long lo, hi;
            LDSV2(lo, hi, addr + 16u * (unsigned)u);
            #pragma unroll
            for (int j = 0; j < 8; j++) {
                const int m = u - j;
                if (m >= 0 && m < 16) {
                    FFMA2(accL[j], lo, kp[2 * m]);
                    FFMA2(accH[j], hi, kp[2 * m + 1]);
                }
            }
        }

        #pragma unroll
        for (int j = 0; j < 8; j++) {
            float l0, l1, h0, h1;
            asm("mov.b64 {%0, %1}, %2;" : "=f"(l0), "=f"(l1) : "l"(accL[j]));
            asm("mov.b64 {%0, %1}, %2;" : "=f"(h0), "=f"(h1) : "l"(accH[j]));
            float y = (l0 + l1) + (h0 + h1);
            chunkacc += fmaxf(y, 0.0f);
        }
    }

    const int j = grp * GROUP + g;
    if (j < NCHUNK)
        S_buf[(b * NCHUNK + j) * CCH + c] = chunkacc;
}

// ---------------- kernel C: merged gather + warp scan, one block per batch ----------------
// 256 threads. Dynamic smem: sCurB (6448 f) | sSufW (18304 f).
// phase 0: stage SufW into smem + AN offsets; phase 1: gather from SMEM;
// phase 2: warp 0 runs the 124-step LIF scan with IC/AC weights in registers.
__global__ void __launch_bounds__(256) scan_kernel(const float* __restrict__ Wic,
                                                   const float* __restrict__ Wac,
                                                   float* __restrict__ out, int half) {
    const int b = blockIdx.x;
    extern __shared__ __align__(16) float dyn[];
    float* sCurB = dyn;                 // [TSTEPS * HIDP]
    float* sSufW = dyn + CURB_N;        // [SUFW_N]
    __shared__ unsigned short sOff[TSTEPS * CCH];
    __shared__ __align__(8) float sSpkB[52];
    __shared__ __align__(8) float sSpkIC[52];

    const int tid = threadIdx.x;

    // ---- phase 0a: stage SufW into smem (coalesced float4) ----
    {
        const float4* src = (const float4*)SufW_g;
        float4* dst = (float4*)sSufW;
        for (int i = tid; i < SUFW_N / 4; i += 256) dst[i] = __ldg(src + i);
    }
    // ---- phase 0b: per-(t,c) suffix offsets ----
    for (int x = tid; x < TSTEPS * CCH; x += 256) {
        int t = x >> 5, c = x & 31;
        float s0 = S_buf[(b * NCHUNK + t) * CCH + c];
        float s1 = S_buf[(b * NCHUNK + t + 1) * CCH + c];
        float env = (s0 + s1) * (1.0f / 256.0f);
        int cnt = 0;
        #pragma unroll
        for (int a = 0; a < ANS; a++) {
            float sc = 0.5f + (float)a * (1.0f / 9.0f);
            cnt += (env * sc - 0.5f) > 0.0f;
        }
        sOff[x] = (unsigned short)((c * 11 + (ANS - cnt)) * HIDP);
    }
    __syncthreads();

    // ---- phase 1: bushy input currents gathered from SMEM ----
    const float4* sw4 = (const float4*)sSufW;
    for (int x = tid; x < TSTEPS * (HIDP / 4); x += 256) {
        int t = x / (HIDP / 4);
        int q = x - t * (HIDP / 4);
        const unsigned short* off = &sOff[t * CCH];
        float4 acc0 = make_float4(0.f, 0.f, 0.f, 0.f);
        float4 acc1 = make_float4(0.f, 0.f, 0.f, 0.f);
        #pragma unroll 4
        for (int c = 0; c < CCH; c += 2) {
            float4 v0 = sw4[(off[c] >> 2) + q];
            float4 v1 = sw4[(off[c + 1] >> 2) + q];
            acc0.x += v0.x; acc0.y += v0.y; acc0.z += v0.z; acc0.w += v0.w;
            acc1.x += v1.x; acc1.y += v1.y; acc1.z += v1.z; acc1.w += v1.w;
        }
        float4 r;
        r.x = acc0.x + acc1.x; r.y = acc0.y + acc1.y;
        r.z = acc0.z + acc1.z; r.w = acc0.w + acc1.w;
        *(float4*)&sCurB[t * HIDP + 4 * q] = r;
    }
    __syncthreads();

    if (tid >= 32) return;      // warps 1-7 done
    const int l = tid;

    // ---- load weights into registers (unrolled, compile-time indices) ----
    const bool lane18 = (l < 18);
    const bool lane10 = (l < 10);
    float2 wA[25], wB[25], wC[25];
    {
        const float* rowA = Wic + l * HID;
        const float* rowB = Wic + (lane18 ? (l + 32) : l) * HID;
        const float* rowC = Wac + (lane10 ? l : 0) * HID;
        #pragma unroll
        for (int j = 0; j < 25; j++) {
            wA[j] = make_float2(__ldg(rowA + 2 * j), __ldg(rowA + 2 * j + 1));
            float2 vb = make_float2(__ldg(rowB + 2 * j), __ldg(rowB + 2 * j + 1));
            wB[j] = lane18 ? vb : make_float2(0.f, 0.f);
            wC[j] = make_float2(__ldg(rowC + 2 * j), __ldg(rowC + 2 * j + 1));
        }
    }

    float memB0 = 0.f, memB1 = 0.f, memIC0 = 0.f, memIC1 = 0.f, memAC = 0.f;
    const float beta = 0.95f;

    for (int t = 0; t < TSTEPS; t++) {
        const float* cb = sCurB + t * HIDP;
        // ---- bushy LIF ----
        float cur0 = cb[l];
        float cur1 = cb[32 + l];          // lanes >=18 read pad/junk; never used
        memB0 = fmaf(beta, memB0, cur0);
        memB1 = fmaf(beta, memB1, cur1);
        float s0 = (memB0 > 1.0f) ? 1.0f : 0.0f;
        float s1 = (memB1 > 1.0f) ? 1.0f : 0.0f;
        memB0 -= s0; memB1 -= s1;
        sSpkB[l] = s0;
        if (lane18) sSpkB[32 + l] = s1;
        __syncwarp();

        // ---- inferior colliculus LIF (register weights) ----
        {
            float a0 = 0.f, a1 = 0.f, a2 = 0.f, a3 = 0.f;
            #pragma unroll
            for (int j = 0; j < 25; j++) {
                float2 sp = *(const float2*)&sSpkB[2 * j];
                a0 = fmaf(sp.x, wA[j].x, a0);
                a1 = fmaf(sp.y, wA[j].y, a1);
                a2 = fmaf(sp.x, wB[j].x, a2);
                a3 = fmaf(sp.y, wB[j].y, a3);
            }
            memIC0 = fmaf(beta, memIC0, a0 + a1);
            memIC1 = fmaf(beta, memIC1, a2 + a3);
        }
        float u0 = (memIC0 > 1.0f) ? 1.0f : 0.0f;
        float u1 = (memIC1 > 1.0f) ? 1.0f : 0.0f;
        memIC0 -= u0; memIC1 -= u1;
        sSpkIC[l] = u0;
        if (lane18) sSpkIC[32 + l] = u1;
        __syncwarp();

        // ---- audio cortex LIF + output ----
        {
            float a0 = 0.f, a1 = 0.f;
            #pragma unroll
            for (int j = 0; j < 25; j++) {
                float2 sp = *(const float2*)&sSpkIC[2 * j];
                a0 = fmaf(sp.x, wC[j].x, a0);
                a1 = fmaf(sp.y, wC[j].y, a1);
            }
            memAC = fmaf(beta, memAC, a0 + a1);
            float sa = (memAC > 1.0f) ? 1.0f : 0.0f;
            memAC -= sa;
            if (lane10) {
                int idx = (b * TSTEPS + t) * OUT + l;
                out[idx] = sa;
                out[half + idx] = memAC;
            }
        }
    }
}

// ---------------- launch ----------------
extern "C" void kernel_launch(void* const* d_in, const int* in_sizes, int n_in,
                              void* d_out, int out_size) {
    const float* audio = (const float*)d_in[0];
    const float* gt    = (const float*)d_in[1];
    const float* Wb    = (const float*)d_in[2];
    const float* Wic   = (const float*)d_in[3];
    const float* Wac   = (const float*)d_in[4];
    float* out = (float*)d_out;

    int B = in_sizes[0] / NSAMP;   // 256
    int half = out_size / 2;       // B*T*OUT

    static int smem_set = 0;
    if (!smem_set) {
        cudaFuncSetAttribute(scan_kernel, cudaFuncAttributeMaxDynamicSharedMemorySize,
                             SCAN_DYN_BYTES);
        smem_set = 1;
    }

    prep_kernel<<<7, 256>>>(Wb);
    conv_pool_kernel<<<dim3((NCHUNK + GROUP - 1) / GROUP, B), 256>>>(audio, gt);
    scan_kernel<<<B, 256, SCAN_DYN_BYTES>>>(Wic, Wac, out, half);
}

// round 9
// speedup vs baseline: 1.1870x; 1.1003x over previous
#include <cuda_runtime.h>

// ---------------- problem constants ----------------
#define BATCH   256
#define NSAMP   16000
#define CCH     32
#define KTAP    64
#define NCHUNK  125          // 128-sample chunks covering 16000 samples
#define TSTEPS  124
#define HID     50
#define HIDP    52           // padded row stride
#define OUT     10
#define ANS     10

#define GROUP   8            // chunks per conv block (one per warp)
#define SEG     (GROUP*128)  // 1024 positions per block
#define SWIN    1088         // staged window length per shifted copy
#define SPITCH  1104         // padded copy pitch (floats)
#define NGRPX   16           // conv position groups

// scan kernel dynamic smem layout (floats)
#define BUF1_N  (TSTEPS * HIDP)          // 6448 : bushy cur -> spk (in place)
#define BUF2_N  (TSTEPS * HIDP)          // 6448 : IC cur -> spk (in place)
#define W2IC_N  (HID * 25)               // 1250 float2
#define W2AC_N  (OUT * 25)               // 250 float2
#define BUFAC_N (TSTEPS * OUT * 2)       // 2480 : AC cur->spk | mem
#define SCAN_DYN_FLOATS (BUF1_N + BUF2_N + 2*W2IC_N + 2*W2AC_N + BUFAC_N)
#define SCAN_DYN_BYTES  (SCAN_DYN_FLOATS * 4)

// ---------------- device scratch (no allocs allowed) ----------------
__device__ float  S_buf[BATCH * NCHUNK * CCH];                       // per-chunk relu sums
__device__ __align__(16) float SufW_g[CCH * (ANS + 1) * HIDP];       // padded suffix sums

// ---------------- helpers ----------------
__device__ __forceinline__ unsigned s2u(const void* p) {
    return (unsigned)__cvta_generic_to_shared(p);
}
#define FFMA2(acc, a, b) \
    asm("fma.rn.f32x2 %0, %1, %2, %0;" : "+l"(acc) : "l"(a), "l"(b))
#define LDSV2(lo, hi, addr) \
    asm("ld.shared.v2.b64 {%0, %1}, [%2];" : "=l"(lo), "=l"(hi) : "r"(addr))

// ---------------- kernel B: fused gammatone conv + relu + chunk-sum ----------------
// grid (17, BATCH): blockIdx.x < 16 -> conv tile; blockIdx.x == 16, y == 0 -> prep.
__global__ void __launch_bounds__(256, 2) conv_pool_kernel(const float* __restrict__ audio,
                                                           const float* __restrict__ gt,
                                                           const float* __restrict__ Wb) {
    const int tid = threadIdx.x;

    if (blockIdx.x == NGRPX) {
        // ---- prep block: suffix sums of W_bushy (runs in conv's shadow) ----
        if (blockIdx.y != 0) return;
        for (int id = tid; id < 1792; id += 256) {
            if (id < CCH * (ANS + 1)) {           // zero pad columns
                SufW_g[id * HIDP + 50] = 0.0f;
                SufW_g[id * HIDP + 51] = 0.0f;
            }
            if (id < HID * CCH) {
                int h = id / CCH;
                int c = id % CCH;
                SufW_g[(c * 11 + 10) * HIDP + h] = 0.0f;
                float v[ANS];
                #pragma unroll
                for (int a = 0; a < ANS; a++)
                    v[a] = Wb[h * (CCH * ANS) + c * ANS + a];
                float s = 0.0f;
                #pragma unroll
                for (int a = ANS - 1; a >= 0; a--) {
                    s += v[a];
                    SufW_g[(c * 11 + a) * HIDP + h] = s;
                }
            }
        }
        return;
    }

    const int grp = blockIdx.x;
    const int b   = blockIdx.y;
    __shared__ __align__(16) float s_copy[4][SPITCH];  // 4 shifted copies of audio window
    __shared__ float s_gt[KTAP * 33];                  // swizzled taps [k*33+c]

    const int P0  = grp * SEG;
    const float* abase = audio + b * NSAMP;

    #pragma unroll
    for (int s = 0; s < 4; s++) {
        for (int i = tid; i < SWIN; i += 256) {
            int n = P0 - 31 + i + s;
            s_copy[s][i] = (n >= 0 && n < NSAMP) ? abase[n] : 0.0f;
        }
    }
    for (int t = tid; t < CCH * KTAP; t += 256) {
        int c = t >> 6, k = t & 63;
        s_gt[k * 33 + c] = gt[t];
    }
    __syncthreads();

    const int c = tid & 31;   // channel = lane
    const int g = tid >> 5;   // warp id = local chunk

    unsigned long long kp[32];
    #pragma unroll
    for (int j = 0; j < 32; j++) {
        float t0 = s_gt[(2 * j) * 33 + c];
        float t1 = s_gt[(2 * j + 1) * 33 + c];
        asm("mov.b64 %0, {%1, %2};" : "=l"(kp[j]) : "f"(t0), "f"(t1));
    }

    const unsigned sbase = s2u(&s_copy[0][0]);
    float chunkacc = 0.0f;

    #pragma unroll 1
    for (int pass = 0; pass < 16; pass++) {
        const int h  = pass >> 2;
        const int c4 = pass & 3;
        const int base = g * 128 + 32 * h;
        const unsigned addr = sbase + (unsigned)((c4 * SPITCH + base) * 4);

        unsigned long long accL[8], accH[8];
        #pragma unroll
        for (int j = 0; j < 8; j++) { accL[j] = 0ull; accH[j] = 0ull; }

        #pragma unroll
        for (int u = 0; u < 23; u++) {
            unsigned long long lo, hi;
            LDSV2(lo, hi, addr + 16u * (unsigned)u);
            #pragma unroll
            for (int j = 0; j < 8; j++) {
                const int m = u - j;
                if (m >= 0 && m < 16) {
                    FFMA2(accL[j], lo, kp[2 * m]);
                    FFMA2(accH[j], hi, kp[2 * m + 1]);
                }
            }
        }

        #pragma unroll
        for (int j = 0; j < 8; j++) {
            float l0, l1, h0, h1;
            asm("mov.b64 {%0, %1}, %2;" : "=f"(l0), "=f"(l1) : "l"(accL[j]));
            asm("mov.b64 {%0, %1}, %2;" : "=f"(h0), "=f"(h1) : "l"(accH[j]));
            float y = (l0 + l1) + (h0 + h1);
            chunkacc += fmaxf(y, 0.0f);
        }
    }

    const int j = grp * GROUP + g;
    if (j < NCHUNK)
        S_buf[(b * NCHUNK + j) * CCH + c] = chunkacc;
}

// ---------------- kernel C: phase-split LIF scan, one block per batch ----------------
// P0 offsets+weights -> P1 gather curB -> P2 bushy scans (50 indep) ->
// P3 IC GEMM [124x50]x[50x50] -> P4 IC scans -> P5 AC GEMM -> P6 AC scans -> P7 write.
// All dot products keep R6's exact accumulation order (bit-identical results).
__global__ void __launch_bounds__(256) scan_kernel(const float* __restrict__ Wic,
                                                   const float* __restrict__ Wac,
                                                   float* __restrict__ out, int half) {
    const int b = blockIdx.x;
    extern __shared__ __align__(16) float dyn[];
    float*  buf1  = dyn;                                   // [124][52] cur->spk bushy
    float*  buf2  = buf1 + BUF1_N;                         // [124][52] cur->spk IC
    float2* w2ic  = (float2*)(buf2 + BUF2_N);              // [50][25]
    float2* w2ac  = w2ic + W2IC_N;                         // [10][25]
    float*  bufAC = (float*)(w2ac + W2AC_N);               // [124][10] cur->spk | [124][10] mem
    __shared__ unsigned short sOff[TSTEPS * CCH];

    const int tid = threadIdx.x;
    const float beta = 0.95f;

    // ---- P0a: per-(t,c) suffix offsets ----
    for (int x = tid; x < TSTEPS * CCH; x += 256) {
        int t = x >> 5, c = x & 31;
        float s0 = S_buf[(b * NCHUNK + t) * CCH + c];
        float s1 = S_buf[(b * NCHUNK + t + 1) * CCH + c];
        float env = (s0 + s1) * (1.0f / 256.0f);
        int cnt = 0;
        #pragma unroll
        for (int a = 0; a < ANS; a++) {
            float sc = 0.5f + (float)a * (1.0f / 9.0f);
            cnt += (env * sc - 0.5f) > 0.0f;
        }
        sOff[x] = (unsigned short)((c * 11 + (ANS - cnt)) * HIDP);
    }
    // ---- P0b: stage packed weights ----
    for (int i = tid; i < W2IC_N; i += 256) {
        int h = i / 25, j = i % 25;
        w2ic[i] = make_float2(__ldg(Wic + h * HID + 2 * j), __ldg(Wic + h * HID + 2 * j + 1));
    }
    for (int i = tid; i < W2AC_N; i += 256) {
        int o = i / 25, j = i % 25;
        w2ac[i] = make_float2(__ldg(Wac + o * HID + 2 * j), __ldg(Wac + o * HID + 2 * j + 1));
    }
    __syncthreads();

    // ---- P1: gather bushy input currents (L1-resident SufW) ----
    for (int x = tid; x < TSTEPS * (HIDP / 4); x += 256) {
        int t = x / (HIDP / 4);
        int q = x - t * (HIDP / 4);
        const unsigned short* off = &sOff[t * CCH];
        float4 acc0 = make_float4(0.f, 0.f, 0.f, 0.f);
        float4 acc1 = make_float4(0.f, 0.f, 0.f, 0.f);
        #pragma unroll 4
        for (int c = 0; c < CCH; c += 2) {
            float4 v0 = __ldg((const float4*)(SufW_g + off[c] + 4 * q));
            float4 v1 = __ldg((const float4*)(SufW_g + off[c + 1] + 4 * q));
            acc0.x += v0.x; acc0.y += v0.y; acc0.z += v0.z; acc0.w += v0.w;
            acc1.x += v1.x; acc1.y += v1.y; acc1.z += v1.z; acc1.w += v1.w;
        }
        float4 r;
        r.x = acc0.x + acc1.x; r.y = acc0.y + acc1.y;
        r.z = acc0.z + acc1.z; r.w = acc0.w + acc1.w;
        *(float4*)&buf1[t * HIDP + 4 * q] = r;
    }
    __syncthreads();

    // ---- P2: bushy membrane scans (50 independent units) ----
    if (tid < HID) {
        float mem = 0.0f;
        #pragma unroll 4
        for (int t = 0; t < TSTEPS; t++) {
            float cur = buf1[t * HIDP + tid];
            mem = fmaf(beta, mem, cur);
            float spk = (mem > 1.0f) ? 1.0f : 0.0f;
            mem -= spk;
            buf1[t * HIDP + tid] = spk;    // in place: cur -> spk
        }
    }
    __syncthreads();

    // ---- P3: IC input GEMM: cur_ic[t][h] = spkB[t] . Wic[h] ----
    for (int u = tid; u < TSTEPS * 25; u += 256) {
        int t = u / 25;
        int hp = u - t * 25;               // h pair (2hp, 2hp+1)
        const float*  sp2 = &buf1[t * HIDP];
        const float2* wa  = &w2ic[(2 * hp) * 25];
        const float2* wb  = &w2ic[(2 * hp + 1) * 25];
        float a0 = 0.f, a1 = 0.f, a2 = 0.f, a3 = 0.f;
        #pragma unroll
        for (int j = 0; j < 25; j++) {
            float2 sp = *(const float2*)&sp2[2 * j];
            float2 va = wa[j];
            float2 vb = wb[j];
            a0 = fmaf(sp.x, va.x, a0);
            a1 = fmaf(sp.y, va.y, a1);
            a2 = fmaf(sp.x, vb.x, a2);
            a3 = fmaf(sp.y, vb.y, a3);
        }
        buf2[t * HIDP + 2 * hp]     = a0 + a1;
        buf2[t * HIDP + 2 * hp + 1] = a2 + a3;
    }
    __syncthreads();

    // ---- P4: IC membrane scans ----
    if (tid < HID) {
        float mem = 0.0f;
        #pragma unroll 4
        for (int t = 0; t < TSTEPS; t++) {
            float cur = buf2[t * HIDP + tid];
            mem = fmaf(beta, mem, cur);
            float spk = (mem > 1.0f) ? 1.0f : 0.0f;
            mem -= spk;
            buf2[t * HIDP + tid] = spk;
        }
    }
    __syncthreads();

    // ---- P5: AC input GEMM: cur_ac[t][o] = spkIC[t] . Wac[o] ----
    for (int u = tid; u < TSTEPS * OUT; u += 256) {
        int t = u / OUT;
        int o = u - t * OUT;
        const float*  sp2 = &buf2[t * HIDP];
        const float2* wc  = &w2ac[o * 25];
        float a0 = 0.f, a1 = 0.f;
        #pragma unroll
        for (int j = 0; j < 25; j++) {
            float2 sp = *(const float2*)&sp2[2 * j];
            float2 vc = wc[j];
            a0 = fmaf(sp.x, vc.x, a0);
            a1 = fmaf(sp.y, vc.y, a1);
        }
        bufAC[t * OUT + o] = a0 + a1;
    }
    __syncthreads();

    // ---- P6: AC membrane scans (10 units) ----
    if (tid < OUT) {
        float mem = 0.0f;
        #pragma unroll 4
        for (int t = 0; t < TSTEPS; t++) {
            float cur = bufAC[t * OUT + tid];
            mem = fmaf(beta, mem, cur);
            float spk = (mem > 1.0f) ? 1.0f : 0.0f;
            mem -= spk;
            bufAC[t * OUT + tid] = spk;                    // in place
            bufAC[TSTEPS * OUT + t * OUT + tid] = mem;     // mem record
        }
    }
    __syncthreads();

    // ---- P7: coalesced output ----
    for (int i = tid; i < TSTEPS * OUT; i += 256) {
        out[b * (TSTEPS * OUT) + i]        = bufAC[i];
        out[half + b * (TSTEPS * OUT) + i] = bufAC[TSTEPS * OUT + i];
    }
}

// ---------------- launch ----------------
extern "C" void kernel_launch(void* const* d_in, const int* in_sizes, int n_in,
                              void* d_out, int out_size) {
    const float* audio = (const float*)d_in[0];
    const float* gt    = (const float*)d_in[1];
    const float* Wb    = (const float*)d_in[2];
    const float* Wic   = (const float*)d_in[3];
    const float* Wac   = (const float*)d_in[4];
    float* out = (float*)d_out;

    int B = in_sizes[0] / NSAMP;   // 256
    int half = out_size / 2;       // B*T*OUT

    static int smem_set = 0;
    if (!smem_set) {
        cudaFuncSetAttribute(scan_kernel, cudaFuncAttributeMaxDynamicSharedMemorySize,
                             SCAN_DYN_BYTES);
        smem_set = 1;
    }

    conv_pool_kernel<<<dim3(NGRPX + 1, B), 256>>>(audio, gt, Wb);
    scan_kernel<<<B, 256, SCAN_DYN_BYTES>>>(Wic, Wac, out, half);
}

// round 10
// speedup vs baseline: 1.2055x; 1.0156x over previous
#include <cuda_runtime.h>

// ---------------- problem constants ----------------
#define BATCH   256
#define NSAMP   16000
#define CCH     32
#define KTAP    64
#define NCHUNK  125          // 128-sample chunks covering 16000 samples
#define TSTEPS  124
#define HID     50
#define HIDP    52           // padded row stride
#define OUT     10
#define ANS     10

#define GROUP   8            // chunks per conv block (one per warp)
#define SEG     (GROUP*128)  // 1024 positions per block
#define SWIN    1088         // staged window length per shifted copy
#define SPITCH  1104         // padded copy pitch (floats)
#define NGRPX   16           // conv position groups

// scan kernel dynamic smem layout (floats)
#define BUF1_N  (TSTEPS * HIDP)          // 6448 : bushy cur -> spk (in place)
#define BUF2_N  (TSTEPS * HIDP)          // 6448 : IC cur -> spk (in place)
#define BUFAC_N (TSTEPS * OUT * 2)       // 2480 : AC cur->spk | mem
#define SCAN_DYN_FLOATS (BUF1_N + BUF2_N + BUFAC_N)
#define SCAN_DYN_BYTES  (SCAN_DYN_FLOATS * 4)

// ---------------- device scratch (no allocs allowed) ----------------
__device__ float  S_buf[BATCH * NCHUNK * CCH];                       // per-chunk relu sums
__device__ __align__(16) float SufW_g[CCH * (ANS + 1) * HIDP];       // padded suffix sums

// ---------------- helpers ----------------
__device__ __forceinline__ unsigned s2u(const void* p) {
    return (unsigned)__cvta_generic_to_shared(p);
}
#define FFMA2(acc, a, b) \
    asm("fma.rn.f32x2 %0, %1, %2, %0;" : "+l"(acc) : "l"(a), "l"(b))
#define LDSV2(lo, hi, addr) \
    asm("ld.shared.v2.b64 {%0, %1}, [%2];" : "=l"(lo), "=l"(hi) : "r"(addr))

// ---------------- kernel B: fused gammatone conv + relu + chunk-sum ----------------
// grid (17, BATCH): blockIdx.x < 16 -> conv tile; blockIdx.x == 16, y == 0 -> prep.
__global__ void __launch_bounds__(256, 2) conv_pool_kernel(const float* __restrict__ audio,
                                                           const float* __restrict__ gt,
                                                           const float* __restrict__ Wb) {
    const int tid = threadIdx.x;

    if (blockIdx.x == NGRPX) {
        // ---- prep block: suffix sums of W_bushy (runs in conv's shadow) ----
        if (blockIdx.y != 0) return;
        for (int id = tid; id < 1792; id += 256) {
            if (id < CCH * (ANS + 1)) {           // zero pad columns
                SufW_g[id * HIDP + 50] = 0.0f;
                SufW_g[id * HIDP + 51] = 0.0f;
            }
            if (id < HID * CCH) {
                int h = id / CCH;
                int c = id % CCH;
                SufW_g[(c * 11 + 10) * HIDP + h] = 0.0f;
                float v[ANS];
                #pragma unroll
                for (int a = 0; a < ANS; a++)
                    v[a] = Wb[h * (CCH * ANS) + c * ANS + a];
                float s = 0.0f;
                #pragma unroll
                for (int a = ANS - 1; a >= 0; a--) {
                    s += v[a];
                    SufW_g[(c * 11 + a) * HIDP + h] = s;
                }
            }
        }
        return;
    }

    const int grp = blockIdx.x;
    const int b   = blockIdx.y;
    __shared__ __align__(16) float s_copy[4][SPITCH];  // 4 shifted copies of audio window
    __shared__ float s_gt[KTAP * 33];                  // swizzled taps [k*33+c]

    const int P0  = grp * SEG;
    const float* abase = audio + b * NSAMP;

    #pragma unroll
    for (int s = 0; s < 4; s++) {
        for (int i = tid; i < SWIN; i += 256) {
            int n = P0 - 31 + i + s;
            s_copy[s][i] = (n >= 0 && n < NSAMP) ? abase[n] : 0.0f;
        }
    }
    for (int t = tid; t < CCH * KTAP; t += 256) {
        int c = t >> 6, k = t & 63;
        s_gt[k * 33 + c] = gt[t];
    }
    __syncthreads();

    const int c = tid & 31;   // channel = lane
    const int g = tid >> 5;   // warp id = local chunk

    unsigned long long kp[32];
    #pragma unroll
    for (int j = 0; j < 32; j++) {
        float t0 = s_gt[(2 * j) * 33 + c];
        float t1 = s_gt[(2 * j + 1) * 33 + c];
        asm("mov.b64 %0, {%1, %2};" : "=l"(kp[j]) : "f"(t0), "f"(t1));
    }

    const unsigned sbase = s2u(&s_copy[0][0]);
    float chunkacc = 0.0f;

    #pragma unroll 1
    for (int pass = 0; pass < 16; pass++) {
        const int h  = pass >> 2;
        const int c4 = pass & 3;
        const int base = g * 128 + 32 * h;
        const unsigned addr = sbase + (unsigned)((c4 * SPITCH + base) * 4);

        unsigned long long accL[8], accH[8];
        #pragma unroll
        for (int j = 0; j < 8; j++) { accL[j] = 0ull; accH[j] = 0ull; }

        #pragma unroll
        for (int u = 0; u < 23; u++) {
            unsigned long long lo, hi;
            LDSV2(lo, hi, addr + 16u * (unsigned)u);
            #pragma unroll
            for (int j = 0; j < 8; j++) {
                const int m = u - j;
                if (m >= 0 && m < 16) {
                    FFMA2(accL[j], lo, kp[2 * m]);
                    FFMA2(accH[j], hi, kp[2 * m + 1]);
                }
            }
        }

        #pragma unroll
        for (int j = 0; j < 8; j++) {
            float l0, l1, h0, h1;
            asm("mov.b64 {%0, %1}, %2;" : "=f"(l0), "=f"(l1) : "l"(accL[j]));
            asm("mov.b64 {%0, %1}, %2;" : "=f"(h0), "=f"(h1) : "l"(accH[j]));
            float y = (l0 + l1) + (h0 + h1);
            chunkacc += fmaxf(y, 0.0f);
        }
    }

    const int j = grp * GROUP + g;
    if (j < NCHUNK)
        S_buf[(b * NCHUNK + j) * CCH + c] = chunkacc;
}

// ---------------- kernel C: phase-split LIF scan, register-weight GEMMs ----------------
// 256 threads per block, one block per batch element.
// P0 offsets -> P1 gather curB -> P2 bushy scans -> P3 IC GEMM (8 warps, reg weights)
// -> P4 IC scans -> P5 AC GEMM -> P6 AC scans -> P7 coalesced write.
__global__ void __launch_bounds__(256, 2) scan_kernel(const float* __restrict__ Wic,
                                                      const float* __restrict__ Wac,
                                                      float* __restrict__ out, int half) {
    const int b = blockIdx.x;
    extern __shared__ __align__(16) float dyn[];
    float* buf1  = dyn;                  // [124][52] bushy cur -> spk
    float* buf2  = buf1 + BUF1_N;        // [124][52] IC cur -> spk
    float* bufAC = buf2 + BUF2_N;        // [124][10] AC spk | [124][10] AC mem
    __shared__ unsigned short sOff[TSTEPS * CCH];

    const int tid = threadIdx.x;
    const int w   = tid >> 5;
    const int l   = tid & 31;
    const float beta = 0.95f;

    // ---- P0: per-(t,c) suffix offsets ----
    for (int x = tid; x < TSTEPS * CCH; x += 256) {
        int t = x >> 5, c = x & 31;
        float s0 = S_buf[(b * NCHUNK + t) * CCH + c];
        float s1 = S_buf[(b * NCHUNK + t + 1) * CCH + c];
        float env = (s0 + s1) * (1.0f / 256.0f);
        int cnt = 0;
        #pragma unroll
        for (int a = 0; a < ANS; a++) {
            float sc = 0.5f + (float)a * (1.0f / 9.0f);
            cnt += (env * sc - 0.5f) > 0.0f;
        }
        sOff[x] = (unsigned short)((c * 11 + (ANS - cnt)) * HIDP);
    }
    __syncthreads();

    // ---- P1: gather bushy input currents (L1-resident SufW) ----
    for (int x = tid; x < TSTEPS * (HIDP / 4); x += 256) {
        int t = x / (HIDP / 4);
        int q = x - t * (HIDP / 4);
        const unsigned short* off = &sOff[t * CCH];
        float4 acc0 = make_float4(0.f, 0.f, 0.f, 0.f);
        float4 acc1 = make_float4(0.f, 0.f, 0.f, 0.f);
        #pragma unroll 4
        for (int c = 0; c < CCH; c += 2) {
            float4 v0 = __ldg((const float4*)(SufW_g + off[c] + 4 * q));
            float4 v1 = __ldg((const float4*)(SufW_g + off[c + 1] + 4 * q));
            acc0.x += v0.x; acc0.y += v0.y; acc0.z += v0.z; acc0.w += v0.w;
            acc1.x += v1.x; acc1.y += v1.y; acc1.z += v1.z; acc1.w += v1.w;
        }
        float4 r;
        r.x = acc0.x + acc1.x; r.y = acc0.y + acc1.y;
        r.z = acc0.z + acc1.z; r.w = acc0.w + acc1.w;
        *(float4*)&buf1[t * HIDP + 4 * q] = r;
    }
    __syncthreads();

    // ---- P2: bushy membrane scans (50 independent units) ----
    if (tid < HID) {
        float mem = 0.0f;
        #pragma unroll 4
        for (int t = 0; t < TSTEPS; t++) {
            float cur = buf1[t * HIDP + tid];
            mem = fmaf(beta, mem, cur);
            float spk = (mem > 1.0f) ? 1.0f : 0.0f;
            mem -= spk;
            buf1[t * HIDP + tid] = spk;    // in place: cur -> spk
        }
    }
    __syncthreads();

    // ---- P3: IC GEMM, register weights, 8 warps strided over t ----
    {
        // sweep A: rows 0..31 (lane l -> row l)
        float2 wR[25];
        {
            const float* row = Wic + l * HID;
            #pragma unroll
            for (int j = 0; j < 25; j++)
                wR[j] = make_float2(__ldg(row + 2 * j), __ldg(row + 2 * j + 1));
        }
        #pragma unroll 1
        for (int t = w; t < TSTEPS; t += 8) {
            const float* sp2 = &buf1[t * HIDP];
            float a0 = 0.f, a1 = 0.f;
            #pragma unroll
            for (int j = 0; j < 25; j++) {
                float2 sp = *(const float2*)&sp2[2 * j];
                a0 = fmaf(sp.x, wR[j].x, a0);
                a1 = fmaf(sp.y, wR[j].y, a1);
            }
            buf2[t * HIDP + l] = a0 + a1;
        }
        // sweep B: rows 32..49 (lane l<18 -> row 32+l)
        {
            const float* row = Wic + (l < 18 ? (l + 32) : l) * HID;
            #pragma unroll
            for (int j = 0; j < 25; j++)
                wR[j] = make_float2(__ldg(row + 2 * j), __ldg(row + 2 * j + 1));
        }
        #pragma unroll 1
        for (int t = w; t < TSTEPS; t += 8) {
            const float* sp2 = &buf1[t * HIDP];
            float a0 = 0.f, a1 = 0.f;
            #pragma unroll
            for (int j = 0; j < 25; j++) {
                float2 sp = *(const float2*)&sp2[2 * j];
                a0 = fmaf(sp.x, wR[j].x, a0);
                a1 = fmaf(sp.y, wR[j].y, a1);
            }
            if (l < 18) buf2[t * HIDP + 32 + l] = a0 + a1;
        }
    }
    __syncthreads();

    // ---- P4: IC membrane scans ----
    if (tid < HID) {
        float mem = 0.0f;
        #pragma unroll 4
        for (int t = 0; t < TSTEPS; t++) {
            float cur = buf2[t * HIDP + tid];
            mem = fmaf(beta, mem, cur);
            float spk = (mem > 1.0f) ? 1.0f : 0.0f;
            mem -= spk;
            buf2[t * HIDP + tid] = spk;
        }
    }
    __syncthreads();

    // ---- P5: AC GEMM, register weights, 8 warps strided over t ----
    {
        float2 wR[25];
        {
            const float* row = Wac + (l < OUT ? l : 0) * HID;
            #pragma unroll
            for (int j = 0; j < 25; j++)
                wR[j] = make_float2(__ldg(row + 2 * j), __ldg(row + 2 * j + 1));
        }
        #pragma unroll 1
        for (int t = w; t < TSTEPS; t += 8) {
            const float* sp2 = &buf2[t * HIDP];
            float a0 = 0.f, a1 = 0.f;
            #pragma unroll
            for (int j = 0; j < 25; j++) {
                float2 sp = *(const float2*)&sp2[2 * j];
                a0 = fmaf(sp.x, wR[j].x, a0);
                a1 = fmaf(sp.y, wR[j].y, a1);
            }
            if (l < OUT) bufAC[t * OUT + l] = a0 + a1;
        }
    }
    __syncthreads();

    // ---- P6: AC membrane scans (10 units) ----
    if (tid < OUT) {
        float mem = 0.0f;
        #pragma unroll 4
        for (int t = 0; t < TSTEPS; t++) {
            float cur = bufAC[t * OUT + tid];
            mem = fmaf(beta, mem, cur);
            float spk = (mem > 1.0f) ? 1.0f : 0.0f;
            mem -= spk;
            bufAC[t * OUT + tid] = spk;                    // in place
            bufAC[TSTEPS * OUT + t * OUT + tid] = mem;     // mem record
        }
    }
    __syncthreads();

    // ---- P7: coalesced output ----
    for (int i = tid; i < TSTEPS * OUT; i += 256) {
        out[b * (TSTEPS * OUT) + i]        = bufAC[i];
        out[half + b * (TSTEPS * OUT) + i] = bufAC[TSTEPS * OUT + i];
    }
}

// ---------------- launch ----------------
extern "C" void kernel_launch(void* const* d_in, const int* in_sizes, int n_in,
                              void* d_out, int out_size) {
    const float* audio = (const float*)d_in[0];
    const float* gt    = (const float*)d_in[1];
    const float* Wb    = (const float*)d_in[2];
    const float* Wic   = (const float*)d_in[3];
    const float* Wac   = (const float*)d_in[4];
    float* out = (float*)d_out;

    int B = in_sizes[0] / NSAMP;   // 256
    int half = out_size / 2;       // B*T*OUT

    static int smem_set = 0;
    if (!smem_set) {
        cudaFuncSetAttribute(scan_kernel, cudaFuncAttributeMaxDynamicSharedMemorySize,
                             SCAN_DYN_BYTES);
        smem_set = 1;
    }

    conv_pool_kernel<<<dim3(NGRPX + 1, B), 256>>>(audio, gt, Wb);
    scan_kernel<<<B, 256, SCAN_DYN_BYTES>>>(Wic, Wac, out, half);
}